// round 6
// baseline (speedup 1.0000x reference)
#include <cuda_runtime.h>
#include <math_constants.h>

// ChamferLoss bidirectional, single pass over the 16384x16384 d2 matrix.
// d2 = (|y|^2 - 2 x.y) + |x|^2 computed with packed fma.rn.f32x2 (2 gt cols
// per lane-pair). Each thread owns 16 gt columns in registers (col-min
// accumulators stay in regs); pred rows are broadcast from smem; row-min via
// warp shuffle per row. Both direction mins extracted from ONE pass.

#define NPTS        16384
#define NROWG       128          // row groups (pred)
#define NCOLG       4            // col groups (gt)
#define ROWS_PB     128          // rows per block
#define COLS_PT     16           // gt cols per thread
#define THREADS     256          // => 4096 cols per block

typedef unsigned long long ull;

__device__ float g_rowpartial[NCOLG * 8][NPTS];   // [colgroup*8+warp][row]
__device__ float g_colpartial[NROWG][NPTS];       // [rowgroup][col]
__device__ float g_bsum[32];

union F2U { ull u; float2 f; };

__device__ __forceinline__ ull pack2(float a, float b) {
    ull r; asm("mov.b64 %0, {%1, %2};" : "=l"(r) : "f"(a), "f"(b)); return r;
}
__device__ __forceinline__ ull fma2(ull a, ull b, ull c) {
    ull d; asm("fma.rn.f32x2 %0, %1, %2, %3;" : "=l"(d) : "l"(a), "l"(b), "l"(c)); return d;
}
__device__ __forceinline__ ull add2(ull a, ull b) {
    ull d; asm("add.rn.f32x2 %0, %1, %2;" : "=l"(d) : "l"(a), "l"(b)); return d;
}

__global__ __launch_bounds__(THREADS, 2)
void chamfer_bidir_kernel(const float* __restrict__ pred,
                          const float* __restrict__ gt) {
    __shared__ float4 rowsm[ROWS_PB][2];     // per row: {a0,a0,a1,a1},{a2,a2,x2,x2}
    __shared__ float  smpart[8][ROWS_PB];    // per-warp row-min partials

    int tid  = threadIdx.x;
    int lane = tid & 31;
    int wid  = tid >> 5;
    int rg   = blockIdx.x & (NROWG - 1);     // 0..127
    int cg   = blockIdx.x >> 7;              // 0..3

    // ---- stage 128 pred rows into smem (duplicated for f32x2 broadcast) ----
    if (tid < ROWS_PB) {
        int r = rg * ROWS_PB + tid;
        float a0 = pred[3*r+0], a1 = pred[3*r+1], a2 = pred[3*r+2];
        float x2 = a0*a0 + a1*a1 + a2*a2;
        rowsm[tid][0] = make_float4(a0, a0, a1, a1);
        rowsm[tid][1] = make_float4(a2, a2, x2, x2);
    }

    // ---- load 16 gt columns into registers, packed 2-per-f32x2 ----
    ull B0[8], B1[8], B2[8], Y2[8];
    int cbase = cg * (THREADS * COLS_PT) + tid * COLS_PT;
    {
        float c[48];
        const float4* g4 = (const float4*)(gt + 3 * cbase);   // 192B, aligned
        #pragma unroll
        for (int k = 0; k < 12; ++k) {
            float4 v = g4[k];
            c[4*k+0] = v.x; c[4*k+1] = v.y; c[4*k+2] = v.z; c[4*k+3] = v.w;
        }
        #pragma unroll
        for (int u = 0; u < 8; ++u) {
            float p0 = c[6*u+0], p1 = c[6*u+1], p2 = c[6*u+2];
            float q0 = c[6*u+3], q1 = c[6*u+4], q2 = c[6*u+5];
            B0[u] = pack2(-2.0f*p0, -2.0f*q0);
            B1[u] = pack2(-2.0f*p1, -2.0f*q1);
            B2[u] = pack2(-2.0f*p2, -2.0f*q2);
            Y2[u] = pack2(p0*p0 + p1*p1 + p2*p2, q0*q0 + q1*q1 + q2*q2);
        }
    }

    float cmin[COLS_PT];
    #pragma unroll
    for (int k = 0; k < COLS_PT; ++k) cmin[k] = CUDART_INF_F;

    __syncthreads();

    // ---- main loop: stream rows, compute full d2, update both mins ----
    #pragma unroll 2
    for (int r = 0; r < ROWS_PB; ++r) {
        const ulonglong2* rp = (const ulonglong2*)&rowsm[r][0];
        ulonglong2 ra = rp[0];           // broadcast LDS.128
        ulonglong2 rb = rp[1];
        ull A0 = ra.x, A1 = ra.y, A2 = rb.x, X2 = rb.y;

        float rm = CUDART_INF_F;
        #pragma unroll
        for (int u = 0; u < 8; ++u) {
            F2U d;
            d.u = add2(fma2(B0[u], A0, fma2(B1[u], A1, fma2(B2[u], A2, Y2[u]))), X2);
            rm = fminf(rm, d.f.x);
            rm = fminf(rm, d.f.y);
            cmin[2*u+0] = fminf(cmin[2*u+0], d.f.x);
            cmin[2*u+1] = fminf(cmin[2*u+1], d.f.y);
        }
        // warp-wide row min (this warp's 512-column slice)
        #pragma unroll
        for (int o = 16; o; o >>= 1)
            rm = fminf(rm, __shfl_xor_sync(0xFFFFFFFFu, rm, o));
        if (lane == 0) smpart[wid][r] = rm;
    }
    __syncthreads();

    // ---- write row partials (coalesced) ----
    for (int idx = tid; idx < 8 * ROWS_PB; idx += THREADS) {
        int w = idx >> 7, rr = idx & (ROWS_PB - 1);
        g_rowpartial[cg*8 + w][rg*ROWS_PB + rr] = smpart[w][rr];
    }
    // ---- write col partials (vectorized) ----
    float4* cp4 = (float4*)&g_colpartial[rg][cbase];
    const float4* cm4 = (const float4*)cmin;
    #pragma unroll
    for (int k = 0; k < 4; ++k) cp4[k] = cm4[k];
}

__global__ void reduce1_kernel() {
    __shared__ float ssum[1024];
    int bid = blockIdx.x;                 // 0..31: 0-15 rows, 16-31 cols
    int i   = (bid & 15) * 1024 + threadIdx.x;

    float m = CUDART_INF_F;
    if (bid < 16) {
        #pragma unroll
        for (int s = 0; s < NCOLG * 8; ++s) m = fminf(m, g_rowpartial[s][i]);
    } else {
        #pragma unroll 8
        for (int s = 0; s < NROWG; ++s) m = fminf(m, g_colpartial[s][i]);
    }
    float v = sqrtf(fmaxf(m, 0.0f));

    ssum[threadIdx.x] = v;
    __syncthreads();
    for (int s = 512; s > 0; s >>= 1) {
        if (threadIdx.x < s) ssum[threadIdx.x] += ssum[threadIdx.x + s];
        __syncthreads();
    }
    if (threadIdx.x == 0) g_bsum[bid] = ssum[0];
}

__global__ void reduce2_kernel(float* __restrict__ out) {
    float s = 0.0f;
    #pragma unroll
    for (int k = 0; k < 32; ++k) s += g_bsum[k];
    out[0] = s * (1.0f / 16384.0f);
}

extern "C" void kernel_launch(void* const* d_in, const int* in_sizes, int n_in,
                              void* d_out, int out_size) {
    const float* pred = (const float*)d_in[0];
    const float* gt   = (const float*)d_in[1];
    chamfer_bidir_kernel<<<NROWG * NCOLG, THREADS>>>(pred, gt);
    reduce1_kernel<<<32, 1024>>>();
    reduce2_kernel<<<1, 1>>>((float*)d_out);
}